// round 1
// baseline (speedup 1.0000x reference)
#include <cuda_runtime.h>
#include <math.h>

#define A_N 33600
#define G_N 300
#define C_N 80
#define FINF __int_as_float(0x7f800000)

// ---------------- scratch (device globals: no allocation allowed) ----------------
__device__ float g_t[(long long)C_N * A_N];   // class-major logit table: t[c*A + a]
__device__ float g_sall[A_N];
__device__ float g_cx[A_N];
__device__ float g_cy[A_N];
__device__ float g_r[A_N];
__device__ unsigned char g_fg[A_N];
__device__ int   g_cnt[A_N];
__device__ int   g_mgt[A_N];
__device__ float g_miou[A_N];
__device__ int   g_multi[A_N];
__device__ int   g_mcnt;
__device__ int   g_numfg;

// non-contracted fp ops (match XLA's separate mul/add semantics)
__device__ __forceinline__ float f_mul(float a, float b) { return __fmul_rn(a, b); }
__device__ __forceinline__ float f_add(float a, float b) { return __fadd_rn(a, b); }
__device__ __forceinline__ float f_sub(float a, float b) { return __fadd_rn(a, -b); }

struct GTBox { float x, y, tlx, tly, brx, bry, area; };

__device__ __forceinline__ GTBox make_gt(const float* __restrict__ gt, int g) {
    GTBox B;
    float gx = gt[g * 4 + 0], gy = gt[g * 4 + 1], gw = gt[g * 4 + 2], gh = gt[g * 4 + 3];
    B.x = gx; B.y = gy;
    B.tlx = f_sub(gx, f_mul(0.5f, gw));
    B.tly = f_sub(gy, f_mul(0.5f, gh));
    B.brx = f_add(gx, f_mul(0.5f, gw));
    B.bry = f_add(gy, f_mul(0.5f, gh));
    B.area = f_mul(gw, gh);
    return B;
}

__device__ __forceinline__ float masked_iou(const GTBox& B, float4 p, bool fg) {
    float hw = f_mul(0.5f, p.z), hh = f_mul(0.5f, p.w);
    float tlx = fmaxf(B.tlx, f_sub(p.x, hw));
    float tly = fmaxf(B.tly, f_sub(p.y, hh));
    float brx = fminf(B.brx, f_add(p.x, hw));
    float bry = fminf(B.bry, f_add(p.y, hh));
    float w = fmaxf(f_sub(brx, tlx), 0.f);
    float h = fmaxf(f_sub(bry, tly), 0.f);
    float inter = f_mul(w, h);
    float uni = f_sub(f_add(B.area, f_mul(p.z, p.w)), inter);
    float iou = inter / uni;
    return fg ? iou : 0.f;
}

__device__ __forceinline__ bool is_cand(const GTBox& B, float cx, float cy, float r) {
    bool inb = (cx > B.tlx) && (B.brx > cx) && (cy > B.tly) && (B.bry > cy);
    bool inc = (cx > f_sub(B.x, r)) && (f_add(B.x, r) > cx) &&
               (cy > f_sub(B.y, r)) && (f_add(B.y, r) > cy);
    return inb && inc;
}

// ---------------- K0: zero scratch ----------------
__global__ void k_zero() {
    int i = blockIdx.x * blockDim.x + threadIdx.x;
    if (i < A_N) g_cnt[i] = 0;
    if (i == 0) { g_mcnt = 0; g_numfg = 0; }
}

// ---------------- K1: per-anchor prep (one warp per anchor) ----------------
__global__ __launch_bounds__(256) void k_prep(
    const float* __restrict__ cls, const float* __restrict__ obj,
    const float* __restrict__ xs, const float* __restrict__ ys,
    const float* __restrict__ es, const int* __restrict__ pbatch)
{
    int warp = (blockIdx.x * blockDim.x + threadIdx.x) >> 5;
    int lane = threadIdx.x & 31;
    if (warp >= A_N) return;
    int a = warp;
    long long b = (long long)(*pbatch);
    float o = obj[b * A_N + a];
    float so = 1.f / (1.f + expf(-o));
    const float* crow = &cls[(b * A_N + a) * C_N];
    float s = 0.f;
    for (int c = lane; c < C_N; c += 32) {
        float z = crow[c];
        float sz = 1.f / (1.f + expf(-z));
        float p = sqrtf(f_mul(sz, so));
        p = fminf(fmaxf(p, 1e-7f), 1.0f - 1e-7f);
        float lp = logf(p), l1p = log1pf(-p);
        g_t[(long long)c * A_N + a] = f_sub(lp, l1p);
        s = f_add(s, l1p);
    }
#pragma unroll
    for (int off = 16; off; off >>= 1) s = f_add(s, __shfl_down_sync(0xffffffffu, s, off));
    if (lane == 0) {
        g_sall[a] = s;
        float st = es[a];
        g_cx[a] = f_mul(f_add(xs[a], 0.5f), st);
        g_cy[a] = f_mul(f_add(ys[a], 0.5f), st);
        g_r[a]  = f_mul(2.5f, st);
    }
}

// ---------------- K2: fg_any per anchor ----------------
__global__ __launch_bounds__(256) void k_fg(const float* __restrict__ gt) {
    __shared__ float4 sg[G_N];
    for (int i = threadIdx.x; i < G_N; i += blockDim.x)
        sg[i] = ((const float4*)gt)[i];
    __syncthreads();
    int a = blockIdx.x * blockDim.x + threadIdx.x;
    if (a >= A_N) return;
    float xc = g_cx[a], yc = g_cy[a], r = g_r[a];
    bool ab = false, ac = false;
    for (int g = 0; g < G_N; g++) {
        float4 bx = sg[g];
        float hw = f_mul(0.5f, bx.z), hh = f_mul(0.5f, bx.w);
        ab = ab || ((xc > f_sub(bx.x, hw)) && (f_add(bx.x, hw) > xc) &&
                    (yc > f_sub(bx.y, hh)) && (f_add(bx.y, hh) > yc));
        ac = ac || ((xc > f_sub(bx.x, r)) && (f_add(bx.x, r) > xc) &&
                    (yc > f_sub(bx.y, r)) && (f_add(bx.y, r) > yc));
        if (ab && ac) break;
    }
    g_fg[a] = (ab || ac) ? 1 : 0;
}

// ---------------- K3: per-gt top-10 (iou and cost), scatter matches ----------------
__global__ __launch_bounds__(256) void k_topk(
    const float* __restrict__ gt, const int* __restrict__ gtc,
    const float4* __restrict__ pb)
{
    const int g = blockIdx.x;
    __shared__ GTBox sgt;
    __shared__ int scls;
    __shared__ float sC[2560];
    __shared__ int   sI[2560];
    __shared__ float sV[2560];
    __shared__ int sDK;
    if (threadIdx.x == 0) { sgt = make_gt(gt, g); scls = gtc[g]; }
    __syncthreads();
    GTBox B = sgt;
    const float* __restrict__ trow = &g_t[(long long)scls * A_N];
    const float L0 = logf(1e-8f);

    float lc[10], lvv[10]; int li[10];
#pragma unroll
    for (int k = 0; k < 10; k++) { lc[k] = FINF; li[k] = 0x7fffffff; lvv[k] = -FINF; }

    for (int a = threadIdx.x; a < A_N; a += 256) {
        float4 p = pb[a];
        bool fg = g_fg[a] != 0;
        float iou = masked_iou(B, p, fg);
        if (iou > lvv[9]) {
            float v = iou;
#pragma unroll
            for (int k = 0; k < 10; k++) {
                if (v > lvv[k]) { float t2 = lvv[k]; lvv[k] = v; v = t2; }
            }
        }
        float cx = g_cx[a], cy = g_cy[a], r = g_r[a];
        bool cand = is_cand(B, cx, cy, r);
        float lg = (iou > 0.f) ? logf(f_add(iou, 1e-8f)) : L0;
        float cl = -f_add(trow[a], g_sall[a]);
        float c = f_sub(cl, f_mul(3.0f, lg));
        if (!cand) c = f_add(c, 100000.0f);
        if (!fg)   c = f_add(c, 1000000.0f);
        if (c < lc[9] || (c == lc[9] && a < li[9])) {
            float vc = c; int vi = a;
#pragma unroll
            for (int k = 0; k < 10; k++) {
                bool sw = (vc < lc[k]) || (vc == lc[k] && vi < li[k]);
                if (sw) { float tc = lc[k]; int ti = li[k]; lc[k] = vc; li[k] = vi; vc = tc; vi = ti; }
            }
        }
    }
    int t = threadIdx.x;
#pragma unroll
    for (int k = 0; k < 10; k++) { sC[t * 10 + k] = lc[k]; sI[t * 10 + k] = li[k]; sV[t * 10 + k] = lvv[k]; }

    for (int s = 128; s > 0; s >>= 1) {
        __syncthreads();
        if (t < s) {
            int b1 = t * 10, b2 = (t + s) * 10;
            float mc[10]; int mi[10]; float mv[10];
            int i = 0, j = 0;
#pragma unroll
            for (int k = 0; k < 10; k++) {
                float c1 = sC[b1 + min(i, 9)]; int i1 = sI[b1 + min(i, 9)];
                float c2 = sC[b2 + min(j, 9)]; int i2 = sI[b2 + min(j, 9)];
                bool t1 = (j >= 10) || ((i < 10) && ((c1 < c2) || (c1 == c2 && i1 < i2)));
                mc[k] = t1 ? c1 : c2; mi[k] = t1 ? i1 : i2;
                if (t1) i++; else j++;
            }
            int ii = 0, jj = 0;
#pragma unroll
            for (int k = 0; k < 10; k++) {
                float v1 = sV[b1 + min(ii, 9)], v2 = sV[b2 + min(jj, 9)];
                bool t1 = (jj >= 10) || ((ii < 10) && (v1 >= v2));
                mv[k] = t1 ? v1 : v2;
                if (t1) ii++; else jj++;
            }
#pragma unroll
            for (int k = 0; k < 10; k++) { sC[b1 + k] = mc[k]; sI[b1 + k] = mi[k]; sV[b1 + k] = mv[k]; }
        }
    }
    __syncthreads();
    if (t == 0) {
        float su = 0.f;
        for (int k = 0; k < 10; k++) su = f_add(su, sV[k]);
        int dk = (int)su;                 // truncation toward zero, as astype(int32)
        dk = max(1, min(10, dk));
        sDK = dk;
    }
    __syncthreads();
    if (t < sDK) {
        int a = sI[t];
        atomicAdd(&g_cnt[a], 1);
        g_mgt[a] = g;                      // racy only when cnt>1 (then unused)
        bool fg = g_fg[a] != 0;
        g_miou[a] = masked_iou(B, pb[a], fg);
    }
}

// ---------------- K4: finalize single matches, collect multi ----------------
__global__ __launch_bounds__(256) void k_final(const int* __restrict__ gtc, float* __restrict__ out) {
    int a = blockIdx.x * blockDim.x + threadIdx.x;
    if (a >= A_N) return;
    int cnt = g_cnt[a];
    float cls = -1.f, fg = 0.f, iou = 0.f, ind = -1.f;
    if (cnt == 1) {
        int g = g_mgt[a];
        cls = (float)gtc[g]; fg = 1.f; iou = g_miou[a]; ind = (float)g;
        atomicAdd(&g_numfg, 1);
    } else if (cnt > 1) {
        fg = 1.f;
        atomicAdd(&g_numfg, 1);
        int m = atomicAdd(&g_mcnt, 1);
        g_multi[m] = a;
    }
    out[a] = cls;
    out[A_N + a] = fg;
    out[2 * A_N + a] = iou;
    out[3 * A_N + a] = ind;
}

// ---------------- K5: resolve multi-matched anchors (warp per anchor) ----------------
__global__ __launch_bounds__(256) void k_multi(
    const float* __restrict__ gt, const int* __restrict__ gtc,
    const float4* __restrict__ pb, float* __restrict__ out)
{
    int w = (blockIdx.x * blockDim.x + threadIdx.x) >> 5;
    int lane = threadIdx.x & 31;
    int nw = (gridDim.x * blockDim.x) >> 5;
    if (w == 0 && lane == 0) out[4 * A_N] = (float)g_numfg;
    int M = g_mcnt;
    const float L0 = logf(1e-8f);
    for (int e = w; e < M; e += nw) {
        int a = g_multi[e];
        float4 p = pb[a];
        bool fg = g_fg[a] != 0;
        float cx = g_cx[a], cy = g_cy[a], r = g_r[a], sall = g_sall[a];
        float best = -FINF; int bg = 0x7fffffff;
        for (int g = lane; g < G_N; g += 32) {
            GTBox B = make_gt(gt, g);
            float iou = masked_iou(B, p, fg);
            bool cand = is_cand(B, cx, cy, r);
            float lg = (iou > 0.f) ? logf(f_add(iou, 1e-8f)) : L0;
            float cl = -f_add(g_t[(long long)gtc[g] * A_N + a], sall);
            float c = f_sub(cl, f_mul(3.0f, lg));
            if (!cand) c = f_add(c, 100000.0f);
            if (!fg)   c = f_add(c, 1000000.0f);
            if (c > best || (c == best && g < bg)) { best = c; bg = g; }
        }
#pragma unroll
        for (int o = 16; o; o >>= 1) {
            float oc = __shfl_down_sync(0xffffffffu, best, o);
            int og = __shfl_down_sync(0xffffffffu, bg, o);
            if (oc > best || (oc == best && og < bg)) { best = oc; bg = og; }
        }
        bg = __shfl_sync(0xffffffffu, bg, 0);
        if (lane == 0) {
            GTBox B = make_gt(gt, bg);
            float iou = masked_iou(B, p, fg);
            out[a] = (float)gtc[bg];
            out[2 * A_N + a] = iou;
            out[3 * A_N + a] = (float)bg;
        }
    }
}

// ---------------- launch ----------------
extern "C" void kernel_launch(void* const* d_in, const int* in_sizes, int n_in,
                              void* d_out, int out_size) {
    const int*   batch = (const int*)d_in[0];
    const float* gt    = (const float*)d_in[3];
    const int*   gtc   = (const int*)d_in[4];
    const float* pb    = (const float*)d_in[5];
    const float* es    = (const float*)d_in[6];
    const float* xs    = (const float*)d_in[7];
    const float* ys    = (const float*)d_in[8];
    const float* cp    = (const float*)d_in[9];
    const float* op    = (const float*)d_in[10];
    float* out = (float*)d_out;

    k_zero<<<(A_N + 255) / 256, 256>>>();
    k_prep<<<(A_N * 32 + 255) / 256, 256>>>(cp, op, xs, ys, es, batch);
    k_fg<<<(A_N + 255) / 256, 256>>>(gt);
    k_topk<<<G_N, 256>>>(gt, gtc, (const float4*)pb);
    k_final<<<(A_N + 255) / 256, 256>>>(gtc, out);
    k_multi<<<64, 256>>>(gt, gtc, (const float4*)pb, out);
}